// round 5
// baseline (speedup 1.0000x reference)
#include <cuda_runtime.h>
#include <cstdint>
#include <cstdio>

#define B_ 64
#define S_ 64
#define P_ 32
#define D_ 512
#define E_ 512
#define H_ 512
#define H3_ 1536
#define A_ 256
#define NH_ 4
#define OUT_ 16
#define BS_ (B_*S_)

// d_out layout: out[64,16] | states[B,S,2H] | context[B,4096] | alpha_actv[B,NH,S]
#define STATES_OFF 1024
#define CONTEXT_OFF (1024 + BS_*2*H_)
#define ALPHA_OFF (CONTEXT_OFF + B_*NH_*2*H_)

// ---------------- scratch (device globals; no allocation allowed) -------------
__device__ float g_vec[BS_*D_];
__device__ float g_emb[BS_*E_];
__device__ float g_xg[2][BS_*H3_];
__device__ float g_h2[2][2][B_*H_];     // [dir][buf][b*H+j]
__device__ float g_m1[BS_*A_];
// barrier state: 4 groups x (4 leaf counters, 1 root, 32 per-member flags), padded
__device__ unsigned g_leaf[4][4][32];
__device__ unsigned g_root[4][32];
__device__ unsigned g_flag[4][32][32];   // [grp][member][pad] -> 128B per member

typedef unsigned long long ull;

// ---------------- f32x2 helpers (FFMA2: 2x fp32 FMA throughput) ---------------
__device__ __forceinline__ ull pk2(float x){
    ull r;
    asm("mov.b64 %0, {%1, %1};" : "=l"(r) : "f"(x));
    return r;
}
__device__ __forceinline__ void fma2(ull& d, ull a, ull b){
    asm("fma.rn.f32x2 %0, %1, %2, %0;" : "+l"(d) : "l"(a), "l"(b));
}
union U64F2 { ull u; float2 f; };

// ---------------- tree-arrival / fan-out-release grid barrier -----------------
// 32 members: 4 leaves of 8 -> root of 4 -> releaser red.adds 32 padded flags.
// Waiters poll ONLY their own flag line (no shared-line contention).
__device__ __forceinline__ void gbar_v5(unsigned* leafp, unsigned* rootp,
                                        unsigned* flags0, unsigned* myflag,
                                        unsigned target){
    __syncthreads();
    if (threadIdx.x == 0){
        unsigned old;
        asm volatile("atom.acq_rel.gpu.global.add.u32 %0, [%1], 1;"
                     : "=r"(old) : "l"(leafp) : "memory");
        bool released = false;
        if (old == 7u){
            asm volatile("st.relaxed.gpu.global.u32 [%0], 0;" :: "l"(leafp) : "memory");
            unsigned old2;
            asm volatile("atom.acq_rel.gpu.global.add.u32 %0, [%1], 1;"
                         : "=r"(old2) : "l"(rootp) : "memory");
            if (old2 == 3u){
                asm volatile("st.relaxed.gpu.global.u32 [%0], 0;" :: "l"(rootp) : "memory");
                #pragma unroll
                for (int m = 0; m < 32; m++){
                    asm volatile("red.release.gpu.global.add.u32 [%0], 1;"
                                 :: "l"(flags0 + m*32) : "memory");
                }
                released = true;
            }
        }
        if (!released){
            unsigned v; int spins = 0;
            while (true){
                asm volatile("ld.acquire.gpu.global.u32 %0, [%1];"
                             : "=r"(v) : "l"(myflag) : "memory");
                if ((int)(v - target) >= 0) break;
                if (++spins > 4) __nanosleep(64);
            }
        }
    }
    __syncthreads();
}

// ---------------- fused conv + weighted-sum (reads inputs ONCE) ---------------
__global__ __launch_bounds__(256) void k_conv_vec(const float* __restrict__ inp,
                                                  const float* __restrict__ conv_w,
                                                  const float* __restrict__ conv_b){
    extern __shared__ float tile[];          // P_*D_ = 16384 floats = 64KB
    __shared__ float cw[D_];
    __shared__ float convp[P_];
    int bs = blockIdx.x;
    int tid = threadIdx.x;
    const float4* src4 = (const float4*)(inp + (size_t)bs*P_*D_);
    float4* t4 = (float4*)tile;
    for (int i = tid; i < D_; i += 256) cw[i] = conv_w[i];
    for (int i = tid; i < P_*D_/4; i += 256) t4[i] = src4[i];
    __syncthreads();
    int wid = tid >> 5, lane = tid & 31;
    float cb = conv_b[0];
    for (int p = wid; p < P_; p += 8){
        float s = 0.f;
        for (int d = lane; d < D_; d += 32) s += tile[p*D_+d]*cw[d];
        #pragma unroll
        for (int o = 16; o > 0; o >>= 1) s += __shfl_xor_sync(0xffffffffu, s, o);
        if (lane == 0) convp[p] = s + cb;
    }
    __syncthreads();
    for (int d = tid; d < D_; d += 256){
        float acc = 0.f;
        #pragma unroll
        for (int p = 0; p < P_; p++) acc += convp[p]*tile[p*D_+d];
        g_vec[(size_t)bs*D_ + d] = acc;
    }
}

// ---------------- SGEMM (R3 version, proven 140us): C = A * Bw^T --------------
__global__ __launch_bounds__(256, 2) void k_sgemm(const float* __restrict__ A,
                                                  const float* __restrict__ Bw,
                                                  float* __restrict__ C,
                                                  int M, int N, int K,
                                                  const float* __restrict__ bias,
                                                  int doClip, int permA){
    __shared__ float As[2][8][128];
    __shared__ float Bs[2][8][128];
    int tid = threadIdx.x;
    int bx = blockIdx.x, by = blockIdx.y;
    int arow = tid >> 1;
    int acol = (tid & 1) * 4;
    int orow = by*128 + arow;
    int grow = permA ? ((orow & 63)*64 + (orow >> 6)) : orow;
    const float* Ap = A + (size_t)grow*K + acol;
    const float* Bp = Bw + (size_t)(bx*128 + arow)*K + acol;

    float4 av = *(const float4*)Ap;
    float4 bv = *(const float4*)Bp;
    As[0][acol+0][arow]=av.x; As[0][acol+1][arow]=av.y; As[0][acol+2][arow]=av.z; As[0][acol+3][arow]=av.w;
    Bs[0][acol+0][arow]=bv.x; Bs[0][acol+1][arow]=bv.y; Bs[0][acol+2][arow]=bv.z; Bs[0][acol+3][arow]=bv.w;
    __syncthreads();

    int tx = tid & 15, ty = tid >> 4;
    ull acc[8][4];
    #pragma unroll
    for (int i = 0; i < 8; i++){
        #pragma unroll
        for (int j = 0; j < 4; j++) acc[i][j] = 0ULL;
    }

    int nk = K >> 3;
    for (int kt = 0; kt < nk; kt++){
        int cur = kt & 1;
        if (kt + 1 < nk){
            av = *(const float4*)(Ap + (kt+1)*8);
            bv = *(const float4*)(Bp + (kt+1)*8);
        }
        #pragma unroll
        for (int k = 0; k < 8; k++){
            float4 a0 = *(const float4*)&As[cur][k][ty*4];
            float4 a1 = *(const float4*)&As[cur][k][64 + ty*4];
            ull b0 = *(const ull*)&Bs[cur][k][tx*4];
            ull b1 = *(const ull*)&Bs[cur][k][tx*4 + 2];
            ull b2 = *(const ull*)&Bs[cur][k][64 + tx*4];
            ull b3 = *(const ull*)&Bs[cur][k][64 + tx*4 + 2];
            float am[8] = {a0.x,a0.y,a0.z,a0.w,a1.x,a1.y,a1.z,a1.w};
            #pragma unroll
            for (int i = 0; i < 8; i++){
                ull pa = pk2(am[i]);
                fma2(acc[i][0], pa, b0);
                fma2(acc[i][1], pa, b1);
                fma2(acc[i][2], pa, b2);
                fma2(acc[i][3], pa, b3);
            }
        }
        if (kt + 1 < nk){
            int nxt = cur ^ 1;
            As[nxt][acol+0][arow]=av.x; As[nxt][acol+1][arow]=av.y; As[nxt][acol+2][arow]=av.z; As[nxt][acol+3][arow]=av.w;
            Bs[nxt][acol+0][arow]=bv.x; Bs[nxt][acol+1][arow]=bv.y; Bs[nxt][acol+2][arow]=bv.z; Bs[nxt][acol+3][arow]=bv.w;
            __syncthreads();
        }
    }

    int c0 = bx*128 + tx*4;
    float4 bv0 = make_float4(0.f,0.f,0.f,0.f), bv1 = bv0;
    if (bias){ bv0 = *(const float4*)&bias[c0]; bv1 = *(const float4*)&bias[c0+64]; }
    #pragma unroll
    for (int i = 0; i < 8; i++){
        int r = by*128 + ((i < 4) ? (ty*4 + i) : (64 + ty*4 + (i-4)));
        U64F2 u0,u1,u2,u3; u0.u=acc[i][0]; u1.u=acc[i][1]; u2.u=acc[i][2]; u3.u=acc[i][3];
        float4 o0 = make_float4(u0.f.x+bv0.x, u0.f.y+bv0.y, u1.f.x+bv0.z, u1.f.y+bv0.w);
        float4 o1 = make_float4(u2.f.x+bv1.x, u2.f.y+bv1.y, u3.f.x+bv1.z, u3.f.y+bv1.w);
        if (doClip){
            o0.x=fminf(fmaxf(o0.x,-1.f),1.f); o0.y=fminf(fmaxf(o0.y,-1.f),1.f);
            o0.z=fminf(fmaxf(o0.z,-1.f),1.f); o0.w=fminf(fmaxf(o0.w,-1.f),1.f);
            o1.x=fminf(fmaxf(o1.x,-1.f),1.f); o1.y=fminf(fmaxf(o1.y,-1.f),1.f);
            o1.z=fminf(fmaxf(o1.z,-1.f),1.f); o1.w=fminf(fmaxf(o1.w,-1.f),1.f);
        }
        *(float4*)&C[(size_t)r*N + c0] = o0;
        *(float4*)&C[(size_t)r*N + c0 + 64] = o1;
    }
}

// ---------------- persistent bidirectional GRU v5 -----------------------------
// 128 blocks x 256 thr (1 CTA/SM). block = (dir, jc 0..31, bc 0..1) -> 16j x 32b.
// thread = 1j x 2b. weights 96KB + h image 64KB = 160KB smem.
// barrier groups (dir,bc): 32 members, tree arrival + per-waiter flags.
__global__ __launch_bounds__(256) void k_gru(const float* __restrict__ w_hh_f,
                                             const float* __restrict__ w_hh_b,
                                             const float* __restrict__ b_hh_f,
                                             const float* __restrict__ b_hh_b,
                                             float* __restrict__ states){
    extern __shared__ float sm[];
    float4* hs4 = (float4*)(sm + 24576);   // h image: 32 rows x 128 float4 (64KB)

    int blk = blockIdx.x;        // 128
    int dir = blk >> 6;
    int rr = blk & 63;
    int jc = rr >> 1, bc = rr & 1;
    int jbase = jc * 16;
    int bbase = bc * 32;
    int grp = dir*2 + bc;
    int member = jc;             // 0..31
    const float* whh = dir ? w_hh_b : w_hh_f;
    const float* bhh = dir ? b_hh_b : b_hh_f;
    const float* xg = g_xg[dir];
    int tid = threadIdx.x;
    int jp = tid >> 4;           // 0..15
    int bp = tid & 15;           // 0..15
    int j  = jbase + jp;
    int b0 = bbase + bp*2;
    int bL0 = bp*2, bL1 = bp*2 + 1;
    unsigned key = (unsigned)(bp & 7);

    unsigned* leafp  = &g_leaf[grp][member & 3][0];
    unsigned* rootp  = &g_root[grp][0];
    unsigned* flags0 = &g_flag[grp][0][0];
    unsigned* myflag = &g_flag[grp][member][0];
    unsigned fbase = 0;
    if (tid == 0){
        asm volatile("ld.relaxed.gpu.global.u32 %0, [%1];" : "=r"(fbase) : "l"(myflag) : "memory");
    }
    unsigned tgt = fbase + 1u;   // only meaningful in thread 0

    // weights: ulonglong2 idx = ((g*8 + (jp>>1))*128 + kq)*2 + (jp&1)
    // -> a warp's two jp rows sit in adjacent 16B slots (single-wavefront LDS128)
    {
        const float4* w4 = (const float4*)whh;
        float4* d4 = (float4*)sm;
        for (int idx = tid; idx < 48*128; idx += 256){
            int row = idx >> 7;          // g*16 + jl
            int kq = idx & 127;
            int g = row >> 4, jl = row & 15;
            int dst = ((g*8 + (jl>>1))*128 + kq)*2 + (jl & 1);
            d4[dst] = w4[(size_t)(g*H_ + jbase + jl)*128 + kq];
        }
    }

    float bhr = bhh[j], bhz = bhh[H_+j], bhn = bhh[2*H_+j];

    g_h2[dir][0][(size_t)b0*H_ + j]     = 0.f;
    g_h2[dir][0][(size_t)(b0+1)*H_ + j] = 0.f;
    gbar_v5(leafp, rootp, flags0, myflag, tgt); tgt++;

    const ulonglong2* wu = (const ulonglong2*)sm;
    int wbr = ((0*8 + (jp>>1))*128)*2 + (jp & 1);
    int wbz = ((1*8 + (jp>>1))*128)*2 + (jp & 1);
    int wbn = ((2*8 + (jp>>1))*128)*2 + (jp & 1);
    const ulonglong2* h0row = (const ulonglong2*)(hs4 + bL0*128);
    const ulonglong2* h1row = (const ulonglong2*)(hs4 + bL1*128);

    // preload xg for t=0
    int tidx0 = dir ? (S_-1) : 0;
    const float* xA = xg + ((size_t)(tidx0*B_ + b0))*H3_;
    const float* xB = xA + H3_;
    float xr0 = xA[j], xz0 = xA[H_+j], xn0 = xA[2*H_+j];
    float xr1 = xB[j], xz1 = xB[H_+j], xn1 = xB[2*H_+j];

    for (int t = 0; t < S_; t++){
        int tidx = dir ? (S_-1-t) : t;

        // stage this group's 32 h rows (64KB), swizzled
        const float4* hr4 = (const float4*)(g_h2[dir][t & 1] + (size_t)bbase*H_);
        #pragma unroll
        for (int i = 0; i < 16; i++){
            int gi = tid + (i << 8);
            int bb = gi >> 7, kq = gi & 127;
            hs4[bb*128 + (kq ^ ((unsigned)(bb >> 1) & 7u))] = hr4[gi];
        }
        __syncthreads();

        // issue next step's xg loads (hidden under the FMA loop)
        float nxr0=0,nxz0=0,nxn0=0,nxr1=0,nxz1=0,nxn1=0;
        if (t + 1 < S_){
            int ntidx = dir ? (S_-2-t) : (t+1);
            const float* nA = xg + ((size_t)(ntidx*B_ + b0))*H3_;
            const float* nB = nA + H3_;
            nxr0 = nA[j]; nxz0 = nA[H_+j]; nxn0 = nA[2*H_+j];
            nxr1 = nB[j]; nxz1 = nB[H_+j]; nxn1 = nB[2*H_+j];
        }

        ull ar0=0,ar1=0,az0=0,az1=0,an0=0,an1=0;
        #pragma unroll 4
        for (int kq = 0; kq < 128; kq++){
            ulonglong2 hA = h0row[kq ^ key];
            ulonglong2 hB = h1row[kq ^ key];
            int k2 = kq << 1;
            ulonglong2 w;
            w = wu[wbr + k2];
            fma2(ar0, hA.x, w.x); fma2(ar0, hA.y, w.y);
            fma2(ar1, hB.x, w.x); fma2(ar1, hB.y, w.y);
            w = wu[wbz + k2];
            fma2(az0, hA.x, w.x); fma2(az0, hA.y, w.y);
            fma2(az1, hB.x, w.x); fma2(az1, hB.y, w.y);
            w = wu[wbn + k2];
            fma2(an0, hA.x, w.x); fma2(an0, hA.y, w.y);
            fma2(an1, hB.x, w.x); fma2(an1, hB.y, w.y);
        }

        int kqj = j >> 2, jo = j & 3;
        float hp0 = ((const float*)(hs4 + bL0*128 + ((unsigned)kqj ^ key)))[jo];
        float hp1 = ((const float*)(hs4 + bL1*128 + ((unsigned)kqj ^ key)))[jo];

        U64F2 u;
        u.u=ar0; float sr0=u.f.x+u.f.y;  u.u=ar1; float sr1=u.f.x+u.f.y;
        u.u=az0; float sz0=u.f.x+u.f.y;  u.u=az1; float sz1=u.f.x+u.f.y;
        u.u=an0; float sn0=u.f.x+u.f.y;  u.u=an1; float sn1=u.f.x+u.f.y;

        float r0 = 1.f/(1.f+expf(-(xr0 + sr0 + bhr)));
        float r1 = 1.f/(1.f+expf(-(xr1 + sr1 + bhr)));
        float z0 = 1.f/(1.f+expf(-(xz0 + sz0 + bhz)));
        float z1 = 1.f/(1.f+expf(-(xz1 + sz1 + bhz)));
        float n0 = tanhf(xn0 + r0*(sn0 + bhn));
        float n1 = tanhf(xn1 + r1*(sn1 + bhn));
        float h0 = (1.f-z0)*n0 + z0*hp0;
        float h1 = (1.f-z1)*n1 + z1*hp1;

        float* hw = g_h2[dir][(t & 1) ^ 1];
        hw[(size_t)b0*H_ + j]     = h0;
        hw[(size_t)(b0+1)*H_ + j] = h1;
        states[((size_t)b0*S_ + tidx)*(2*H_) + dir*H_ + j]     = h0;
        states[((size_t)(b0+1)*S_ + tidx)*(2*H_) + dir*H_ + j] = h1;

        gbar_v5(leafp, rootp, flags0, myflag, tgt); tgt++;

        xr0=nxr0; xz0=nxz0; xn0=nxn0; xr1=nxr1; xz1=nxz1; xn1=nxn1;
    }
}

// ---------------- alpha = m1 @ att_w2^T, softmax over S -----------------------
__global__ __launch_bounds__(256) void k_alpha(const float* __restrict__ att_w2,
                                               float* __restrict__ alpha_out){
    __shared__ float w2s[NH_*A_];
    __shared__ float al[NH_*S_];
    int b = blockIdx.x, tid = threadIdx.x;
    for (int i = tid; i < NH_*A_; i += 256) w2s[i] = att_w2[i];
    __syncthreads();
    int s = tid >> 2, h = tid & 3;
    const float* m1r = g_m1 + ((size_t)(b*S_ + s))*A_;
    float acc = 0.f;
    #pragma unroll 4
    for (int k = 0; k < A_; k++) acc += m1r[k]*w2s[h*A_+k];
    al[h*S_+s] = acc;
    __syncthreads();
    int wid = tid >> 5, lane = tid & 31;
    if (wid < NH_){
        float v0 = al[wid*S_+lane], v1 = al[wid*S_+lane+32];
        float mx = fmaxf(v0, v1);
        #pragma unroll
        for (int o = 16; o > 0; o >>= 1) mx = fmaxf(mx, __shfl_xor_sync(0xffffffffu, mx, o));
        float e0 = expf(v0-mx), e1 = expf(v1-mx);
        float sm = e0 + e1;
        #pragma unroll
        for (int o = 16; o > 0; o >>= 1) sm += __shfl_xor_sync(0xffffffffu, sm, o);
        float inv = 1.f/sm;
        alpha_out[(b*NH_+wid)*S_ + lane]      = e0*inv;
        alpha_out[(b*NH_+wid)*S_ + lane + 32] = e1*inv;
    }
}

// ---------------- context = alpha @ states ------------------------------------
__global__ __launch_bounds__(512) void k_context(const float* __restrict__ states,
                                                 const float* __restrict__ alpha_in,
                                                 float* __restrict__ context){
    __shared__ float als[NH_*S_];
    int b = blockIdx.x, tid = threadIdx.x;
    if (tid < NH_*S_) als[tid] = alpha_in[b*NH_*S_ + tid];
    __syncthreads();
    float a0[NH_], a1[NH_];
    #pragma unroll
    for (int h = 0; h < NH_; h++){ a0[h] = 0.f; a1[h] = 0.f; }
    const float* st = states + (size_t)b*S_*2*H_;
    for (int s = 0; s < S_; s++){
        float v0 = st[s*2*H_ + tid];
        float v1 = st[s*2*H_ + H_ + tid];
        #pragma unroll
        for (int h = 0; h < NH_; h++){
            float a = als[h*S_+s];
            a0[h] += a*v0; a1[h] += a*v1;
        }
    }
    float* cb = context + (size_t)b*NH_*2*H_;
    #pragma unroll
    for (int h = 0; h < NH_; h++){
        cb[h*2*H_ + tid]      = a0[h];
        cb[h*2*H_ + H_ + tid] = a1[h];
    }
}

// ---------------- final linear + softmax --------------------------------------
__global__ __launch_bounds__(512) void k_final(const float* __restrict__ context,
                                               const float* __restrict__ lin_w,
                                               const float* __restrict__ lin_b,
                                               float* __restrict__ out){
    __shared__ float red[OUT_];
    int b = blockIdx.x, tid = threadIdx.x, w = tid >> 5, lane = tid & 31;
    const float* cx = context + (size_t)b*4096;
    const float* lw = lin_w + (size_t)w*4096;
    float acc = 0.f;
    for (int k = lane; k < 4096; k += 32) acc += cx[k]*lw[k];
    #pragma unroll
    for (int o = 16; o > 0; o >>= 1) acc += __shfl_xor_sync(0xffffffffu, acc, o);
    if (lane == 0) red[w] = acc + lin_b[w];
    __syncthreads();
    if (tid < 32){
        float v = (lane < OUT_) ? red[lane] : -1e30f;
        float mx = v;
        #pragma unroll
        for (int o = 16; o > 0; o >>= 1) mx = fmaxf(mx, __shfl_xor_sync(0xffffffffu, mx, o));
        float e = (lane < OUT_) ? expf(v - mx) : 0.f;
        float sm = e;
        #pragma unroll
        for (int o = 16; o > 0; o >>= 1) sm += __shfl_xor_sync(0xffffffffu, sm, o);
        if (lane < OUT_) out[b*OUT_ + lane] = e/sm;
    }
}

// ---------------- launch ------------------------------------------------------
extern "C" void kernel_launch(void* const* d_in, const int* in_sizes, int n_in,
                              void* d_out, int out_size){
    const float* inputs  = (const float*)d_in[0];
    const float* conv_w  = (const float*)d_in[2];
    const float* conv_b  = (const float*)d_in[3];
    const float* w_embed = (const float*)d_in[4];
    const float* w_ih_f  = (const float*)d_in[5];
    const float* w_hh_f  = (const float*)d_in[6];
    const float* b_ih_f  = (const float*)d_in[7];
    const float* b_hh_f  = (const float*)d_in[8];
    const float* w_ih_b  = (const float*)d_in[9];
    const float* w_hh_b  = (const float*)d_in[10];
    const float* b_ih_b  = (const float*)d_in[11];
    const float* b_hh_b  = (const float*)d_in[12];
    const float* att_w1  = (const float*)d_in[13];
    const float* att_w2  = (const float*)d_in[14];
    const float* lin_w   = (const float*)d_in[15];
    const float* lin_b   = (const float*)d_in[16];

    float* out     = (float*)d_out;
    float* states  = out + STATES_OFF;
    float* context = out + CONTEXT_OFF;
    float* alpha   = out + ALPHA_OFF;

    void *p_vec, *p_emb, *p_xg, *p_m1;
    cudaGetSymbolAddress(&p_vec, g_vec);
    cudaGetSymbolAddress(&p_emb, g_emb);
    cudaGetSymbolAddress(&p_xg,  g_xg);
    cudaGetSymbolAddress(&p_m1,  g_m1);
    float* vec = (float*)p_vec;
    float* emb = (float*)p_emb;
    float* xg0 = (float*)p_xg;
    float* xg1 = xg0 + (size_t)BS_*H3_;
    float* m1  = (float*)p_m1;

    const int conv_smem = P_*D_*4;                     // 65536
    const int gru_smem  = 24576*4 + 32*128*16;         // 96KB + 64KB = 163840
    cudaFuncSetAttribute(k_conv_vec, cudaFuncAttributeMaxDynamicSharedMemorySize, conv_smem);
    cudaFuncSetAttribute(k_gru,      cudaFuncAttributeMaxDynamicSharedMemorySize, gru_smem);

    // 1) conv + weighted-sum (inputs read once)
    k_conv_vec<<<BS_, 256, conv_smem>>>(inputs, conv_w, conv_b);
    // 2) emb = clip(vec @ w_embed^T)
    k_sgemm<<<dim3(E_/128, BS_/128), 256>>>(vec, w_embed, emb, BS_, E_, D_, nullptr, 1, 0);
    // 3) xg = emb([S,B] permuted) @ w_ih^T + b_ih, both directions
    k_sgemm<<<dim3(H3_/128, BS_/128), 256>>>(emb, w_ih_f, xg0, BS_, H3_, E_, b_ih_f, 0, 1);
    k_sgemm<<<dim3(H3_/128, BS_/128), 256>>>(emb, w_ih_b, xg1, BS_, H3_, E_, b_ih_b, 0, 1);
    // 4) persistent bidirectional GRU -> states (written straight into d_out)
    k_gru<<<128, 256, gru_smem>>>(w_hh_f, w_hh_b, b_hh_f, b_hh_b, states);
    // 5) m1 = clip(states @ att_w1^T)
    k_sgemm<<<dim3(A_/128, BS_/128), 256>>>(states, att_w1, m1, BS_, A_, 2*H_, nullptr, 1, 0);
    // 6) alpha = softmax_S(m1 @ att_w2^T), transposed to [B,NH,S]
    k_alpha<<<B_, 256>>>(att_w2, alpha);
    // 7) context
    k_context<<<B_, 512>>>(states, alpha, context);
    // 8) out = softmax(context @ lin_w^T + lin_b)
    k_final<<<B_, 512>>>(context, lin_w, lin_b, out);
}

// round 6
// speedup vs baseline: 1.6424x; 1.6424x over previous
#include <cuda_runtime.h>
#include <cstdint>
#include <cstdio>

#define B_ 64
#define S_ 64
#define P_ 32
#define D_ 512
#define E_ 512
#define H_ 512
#define H3_ 1536
#define A_ 256
#define NH_ 4
#define OUT_ 16
#define BS_ (B_*S_)

// d_out layout: out[64,16] | states[B,S,2H] | context[B,4096] | alpha_actv[B,NH,S]
#define STATES_OFF 1024
#define CONTEXT_OFF (1024 + BS_*2*H_)
#define ALPHA_OFF (CONTEXT_OFF + B_*NH_*2*H_)

// ---------------- scratch (device globals; no allocation allowed) -------------
__device__ float g_vec[BS_*D_];
__device__ float g_emb[BS_*E_];
__device__ float g_xg[2][BS_*H3_];
__device__ float g_h2[2][2][B_*H_];     // [dir][buf][b*H+j]
__device__ float g_m1[BS_*A_];
__device__ unsigned g_cnt8[8][32];      // 8 barrier groups, padded
__device__ unsigned g_gen8[8][32];

typedef unsigned long long ull;

// ---------------- f32x2 helpers (FFMA2: 2x fp32 FMA throughput) ---------------
__device__ __forceinline__ ull pk2(float x){
    ull r;
    asm("mov.b64 %0, {%1, %1};" : "=l"(r) : "f"(x));
    return r;
}
__device__ __forceinline__ void fma2(ull& d, ull a, ull b){
    asm("fma.rn.f32x2 %0, %1, %2, %0;" : "+l"(d) : "l"(a), "l"(b));
}
union U64F2 { ull u; float2 f; };

// ---------------- simple group grid barrier (16 blocks per group, R3-style) ----
__device__ __forceinline__ void gbar_grp(int grp){
    __syncthreads();
    if (threadIdx.x == 0){
        __threadfence();
        unsigned g = *((volatile unsigned*)&g_gen8[grp][0]);
        if (atomicAdd(&g_cnt8[grp][0], 1u) == 15u){
            g_cnt8[grp][0] = 0u;
            __threadfence();
            atomicExch(&g_gen8[grp][0], g + 1u);
        } else {
            while (*((volatile unsigned*)&g_gen8[grp][0]) == g) { }
        }
        __threadfence();
    }
    __syncthreads();
}

// ---------------- fused conv + weighted-sum (reads inputs ONCE) ---------------
__global__ __launch_bounds__(256) void k_conv_vec(const float* __restrict__ inp,
                                                  const float* __restrict__ conv_w,
                                                  const float* __restrict__ conv_b){
    extern __shared__ float tile[];          // P_*D_ = 16384 floats = 64KB
    __shared__ float cw[D_];
    __shared__ float convp[P_];
    int bs = blockIdx.x;
    int tid = threadIdx.x;
    const float4* src4 = (const float4*)(inp + (size_t)bs*P_*D_);
    float4* t4 = (float4*)tile;
    for (int i = tid; i < D_; i += 256) cw[i] = conv_w[i];
    for (int i = tid; i < P_*D_/4; i += 256) t4[i] = src4[i];
    __syncthreads();
    int wid = tid >> 5, lane = tid & 31;
    float cb = conv_b[0];
    for (int p = wid; p < P_; p += 8){
        float s = 0.f;
        for (int d = lane; d < D_; d += 32) s += tile[p*D_+d]*cw[d];
        #pragma unroll
        for (int o = 16; o > 0; o >>= 1) s += __shfl_xor_sync(0xffffffffu, s, o);
        if (lane == 0) convp[p] = s + cb;
    }
    __syncthreads();
    for (int d = tid; d < D_; d += 256){
        float acc = 0.f;
        #pragma unroll
        for (int p = 0; p < P_; p++) acc += convp[p]*tile[p*D_+d];
        g_vec[(size_t)bs*D_ + d] = acc;
    }
}

// ---------------- SGEMM (R3-proven): C = A * Bw^T, optional z-select ----------
// blockIdx.z == 1 -> use Bw2/bias2, write C + M*N (for merged xg_f/xg_b)
__global__ __launch_bounds__(256, 2) void k_sgemm(const float* __restrict__ A,
                                                  const float* __restrict__ Bw,
                                                  const float* __restrict__ Bw2,
                                                  float* __restrict__ C,
                                                  int M, int N, int K,
                                                  const float* __restrict__ bias,
                                                  const float* __restrict__ bias2,
                                                  int doClip, int permA){
    __shared__ float As[2][8][128];
    __shared__ float Bs[2][8][128];
    int tid = threadIdx.x;
    int bx = blockIdx.x, by = blockIdx.y;
    if (blockIdx.z){ Bw = Bw2; bias = bias2; C += (size_t)M*N; }
    int arow = tid >> 1;
    int acol = (tid & 1) * 4;
    int orow = by*128 + arow;
    int grow = permA ? ((orow & 63)*64 + (orow >> 6)) : orow;
    const float* Ap = A + (size_t)grow*K + acol;
    const float* Bp = Bw + (size_t)(bx*128 + arow)*K + acol;

    float4 av = *(const float4*)Ap;
    float4 bv = *(const float4*)Bp;
    As[0][acol+0][arow]=av.x; As[0][acol+1][arow]=av.y; As[0][acol+2][arow]=av.z; As[0][acol+3][arow]=av.w;
    Bs[0][acol+0][arow]=bv.x; Bs[0][acol+1][arow]=bv.y; Bs[0][acol+2][arow]=bv.z; Bs[0][acol+3][arow]=bv.w;
    __syncthreads();

    int tx = tid & 15, ty = tid >> 4;
    ull acc[8][4];
    #pragma unroll
    for (int i = 0; i < 8; i++){
        #pragma unroll
        for (int j = 0; j < 4; j++) acc[i][j] = 0ULL;
    }

    int nk = K >> 3;
    for (int kt = 0; kt < nk; kt++){
        int cur = kt & 1;
        if (kt + 1 < nk){
            av = *(const float4*)(Ap + (kt+1)*8);
            bv = *(const float4*)(Bp + (kt+1)*8);
        }
        #pragma unroll
        for (int k = 0; k < 8; k++){
            float4 a0 = *(const float4*)&As[cur][k][ty*4];
            float4 a1 = *(const float4*)&As[cur][k][64 + ty*4];
            ull b0 = *(const ull*)&Bs[cur][k][tx*4];
            ull b1 = *(const ull*)&Bs[cur][k][tx*4 + 2];
            ull b2 = *(const ull*)&Bs[cur][k][64 + tx*4];
            ull b3 = *(const ull*)&Bs[cur][k][64 + tx*4 + 2];
            float am[8] = {a0.x,a0.y,a0.z,a0.w,a1.x,a1.y,a1.z,a1.w};
            #pragma unroll
            for (int i = 0; i < 8; i++){
                ull pa = pk2(am[i]);
                fma2(acc[i][0], pa, b0);
                fma2(acc[i][1], pa, b1);
                fma2(acc[i][2], pa, b2);
                fma2(acc[i][3], pa, b3);
            }
        }
        if (kt + 1 < nk){
            int nxt = cur ^ 1;
            As[nxt][acol+0][arow]=av.x; As[nxt][acol+1][arow]=av.y; As[nxt][acol+2][arow]=av.z; As[nxt][acol+3][arow]=av.w;
            Bs[nxt][acol+0][arow]=bv.x; Bs[nxt][acol+1][arow]=bv.y; Bs[nxt][acol+2][arow]=bv.z; Bs[nxt][acol+3][arow]=bv.w;
            __syncthreads();
        }
    }

    int c0 = bx*128 + tx*4;
    float4 bv0 = make_float4(0.f,0.f,0.f,0.f), bv1 = bv0;
    if (bias){ bv0 = *(const float4*)&bias[c0]; bv1 = *(const float4*)&bias[c0+64]; }
    #pragma unroll
    for (int i = 0; i < 8; i++){
        int r = by*128 + ((i < 4) ? (ty*4 + i) : (64 + ty*4 + (i-4)));
        U64F2 u0,u1,u2,u3; u0.u=acc[i][0]; u1.u=acc[i][1]; u2.u=acc[i][2]; u3.u=acc[i][3];
        float4 o0 = make_float4(u0.f.x+bv0.x, u0.f.y+bv0.y, u1.f.x+bv0.z, u1.f.y+bv0.w);
        float4 o1 = make_float4(u2.f.x+bv1.x, u2.f.y+bv1.y, u3.f.x+bv1.z, u3.f.y+bv1.w);
        if (doClip){
            o0.x=fminf(fmaxf(o0.x,-1.f),1.f); o0.y=fminf(fmaxf(o0.y,-1.f),1.f);
            o0.z=fminf(fmaxf(o0.z,-1.f),1.f); o0.w=fminf(fmaxf(o0.w,-1.f),1.f);
            o1.x=fminf(fmaxf(o1.x,-1.f),1.f); o1.y=fminf(fmaxf(o1.y,-1.f),1.f);
            o1.z=fminf(fmaxf(o1.z,-1.f),1.f); o1.w=fminf(fmaxf(o1.w,-1.f),1.f);
        }
        *(float4*)&C[(size_t)r*N + c0] = o0;
        *(float4*)&C[(size_t)r*N + c0 + 64] = o1;
    }
}

// ---------------- persistent bidirectional GRU v6 -----------------------------
// 128 blocks x 256 thr (1 CTA/SM). block = (dir, jc 0..15, bq 0..3) -> 32j x 16b.
// thread = 1j x 2b. weights 192KB (4-row interleave) + h image 32KB = 224KB.
// 8 barrier groups (dir,bq) of 16 blocks; R3's simple barrier.
__global__ __launch_bounds__(256) void k_gru(const float* __restrict__ w_hh_f,
                                             const float* __restrict__ w_hh_b,
                                             const float* __restrict__ b_hh_f,
                                             const float* __restrict__ b_hh_b,
                                             float* __restrict__ states){
    extern __shared__ float sm[];
    float4* hs4 = (float4*)(sm + 49152);   // h image: 16 rows x 128 float4 (32KB)

    int blk = blockIdx.x;        // 128
    int dir = blk >> 6;
    int rr = blk & 63;
    int jc = rr >> 2, bq = rr & 3;
    int jbase = jc * 32;
    int bbase = bq * 16;
    int grp = dir*4 + bq;        // 0..7
    const float* whh = dir ? w_hh_b : w_hh_f;
    const float* bhh = dir ? b_hh_b : b_hh_f;
    const float* xg = g_xg[dir];
    int tid = threadIdx.x;
    int jp = tid >> 3;           // 0..31
    int bp = tid & 7;            // 0..7
    int j  = jbase + jp;
    int b0 = bbase + bp*2;
    int bL0 = bp*2, bL1 = bp*2 + 1;
    unsigned key = (unsigned)bp;  // 0..7

    // weights: 96 rows (g*32 + jl). float4 dst = ((g*8 + (jl>>2))*128 + kq)*4 + (jl&3)
    // -> a warp's 4 jp rows sit in 4 consecutive 16B slots (single-wavefront LDS128)
    {
        const float4* w4 = (const float4*)whh;
        float4* d4 = (float4*)sm;
        for (int idx = tid; idx < 96*128; idx += 256){
            int row = idx >> 7;          // g*32 + jl
            int kq = idx & 127;
            int g = row >> 5, jl = row & 31;
            int dst = ((g*8 + (jl>>2))*128 + kq)*4 + (jl & 3);
            d4[dst] = w4[(size_t)(g*H_ + jbase + jl)*128 + kq];
        }
    }

    float bhr = bhh[j], bhz = bhh[H_+j], bhn = bhh[2*H_+j];

    g_h2[dir][0][(size_t)b0*H_ + j]     = 0.f;
    g_h2[dir][0][(size_t)(b0+1)*H_ + j] = 0.f;
    gbar_grp(grp);

    const ulonglong2* wu = (const ulonglong2*)sm;
    int wbr = ((0*8 + (jp>>2))*128)*4 + (jp & 3);
    int wbz = ((1*8 + (jp>>2))*128)*4 + (jp & 3);
    int wbn = ((2*8 + (jp>>2))*128)*4 + (jp & 3);
    const ulonglong2* h0row = (const ulonglong2*)(hs4 + bL0*128);
    const ulonglong2* h1row = (const ulonglong2*)(hs4 + bL1*128);

    // preload xg for t=0
    int tidx0 = dir ? (S_-1) : 0;
    {
    }
    const float* xA0 = xg + ((size_t)(tidx0*B_ + b0))*H3_;
    const float* xB0 = xA0 + H3_;
    float xr0 = xA0[j], xz0 = xA0[H_+j], xn0 = xA0[2*H_+j];
    float xr1 = xB0[j], xz1 = xB0[H_+j], xn1 = xB0[2*H_+j];

    for (int t = 0; t < S_; t++){
        int tidx = dir ? (S_-1-t) : t;

        // stage this group's 16 h rows (32KB), coalesced LDG -> swizzled STS
        const float4* hr4 = (const float4*)(g_h2[dir][t & 1] + (size_t)bbase*H_);
        #pragma unroll
        for (int i = 0; i < 8; i++){
            int gi = tid + (i << 8);
            int bb = gi >> 7, kq = gi & 127;
            hs4[bb*128 + (kq ^ ((unsigned)(bb >> 1) & 7u))] = hr4[gi];
        }
        __syncthreads();

        // issue next step's xg loads (hidden under the FMA loop)
        float nxr0=0,nxz0=0,nxn0=0,nxr1=0,nxz1=0,nxn1=0;
        if (t + 1 < S_){
            int ntidx = dir ? (S_-2-t) : (t+1);
            const float* nA = xg + ((size_t)(ntidx*B_ + b0))*H3_;
            const float* nB = nA + H3_;
            nxr0 = nA[j]; nxz0 = nA[H_+j]; nxn0 = nA[2*H_+j];
            nxr1 = nB[j]; nxz1 = nB[H_+j]; nxn1 = nB[2*H_+j];
        }

        ull ar0=0,ar1=0,az0=0,az1=0,an0=0,an1=0;
        #pragma unroll 4
        for (int kq = 0; kq < 128; kq++){
            ulonglong2 hA = h0row[kq ^ key];
            ulonglong2 hB = h1row[kq ^ key];
            int k4 = kq << 2;
            ulonglong2 w;
            w = wu[wbr + k4];
            fma2(ar0, hA.x, w.x); fma2(ar0, hA.y, w.y);
            fma2(ar1, hB.x, w.x); fma2(ar1, hB.y, w.y);
            w = wu[wbz + k4];
            fma2(az0, hA.x, w.x); fma2(az0, hA.y, w.y);
            fma2(az1, hB.x, w.x); fma2(az1, hB.y, w.y);
            w = wu[wbn + k4];
            fma2(an0, hA.x, w.x); fma2(an0, hA.y, w.y);
            fma2(an1, hB.x, w.x); fma2(an1, hB.y, w.y);
        }

        int kqj = j >> 2, jo = j & 3;
        float hp0 = ((const float*)(hs4 + bL0*128 + ((unsigned)kqj ^ key)))[jo];
        float hp1 = ((const float*)(hs4 + bL1*128 + ((unsigned)kqj ^ key)))[jo];

        U64F2 u;
        u.u=ar0; float sr0=u.f.x+u.f.y;  u.u=ar1; float sr1=u.f.x+u.f.y;
        u.u=az0; float sz0=u.f.x+u.f.y;  u.u=az1; float sz1=u.f.x+u.f.y;
        u.u=an0; float sn0=u.f.x+u.f.y;  u.u=an1; float sn1=u.f.x+u.f.y;

        float r0 = 1.f/(1.f+expf(-(xr0 + sr0 + bhr)));
        float r1 = 1.f/(1.f+expf(-(xr1 + sr1 + bhr)));
        float z0 = 1.f/(1.f+expf(-(xz0 + sz0 + bhz)));
        float z1 = 1.f/(1.f+expf(-(xz1 + sz1 + bhz)));
        float n0 = tanhf(xn0 + r0*(sn0 + bhn));
        float n1 = tanhf(xn1 + r1*(sn1 + bhn));
        float h0 = (1.f-z0)*n0 + z0*hp0;
        float h1 = (1.f-z1)*n1 + z1*hp1;

        float* hw = g_h2[dir][(t & 1) ^ 1];
        hw[(size_t)b0*H_ + j]     = h0;
        hw[(size_t)(b0+1)*H_ + j] = h1;
        states[((size_t)b0*S_ + tidx)*(2*H_) + dir*H_ + j]     = h0;
        states[((size_t)(b0+1)*S_ + tidx)*(2*H_) + dir*H_ + j] = h1;

        gbar_grp(grp);

        xr0=nxr0; xz0=nxz0; xn0=nxn0; xr1=nxr1; xz1=nxz1; xn1=nxn1;
    }
}

// ---------------- alpha = m1 @ att_w2^T, softmax over S -----------------------
__global__ __launch_bounds__(256) void k_alpha(const float* __restrict__ att_w2,
                                               float* __restrict__ alpha_out){
    __shared__ float w2s[NH_*A_];
    __shared__ float al[NH_*S_];
    int b = blockIdx.x, tid = threadIdx.x;
    for (int i = tid; i < NH_*A_; i += 256) w2s[i] = att_w2[i];
    __syncthreads();
    int s = tid >> 2, h = tid & 3;
    const float* m1r = g_m1 + ((size_t)(b*S_ + s))*A_;
    float acc = 0.f;
    #pragma unroll 4
    for (int k = 0; k < A_; k++) acc += m1r[k]*w2s[h*A_+k];
    al[h*S_+s] = acc;
    __syncthreads();
    int wid = tid >> 5, lane = tid & 31;
    if (wid < NH_){
        float v0 = al[wid*S_+lane], v1 = al[wid*S_+lane+32];
        float mx = fmaxf(v0, v1);
        #pragma unroll
        for (int o = 16; o > 0; o >>= 1) mx = fmaxf(mx, __shfl_xor_sync(0xffffffffu, mx, o));
        float e0 = expf(v0-mx), e1 = expf(v1-mx);
        float sm = e0 + e1;
        #pragma unroll
        for (int o = 16; o > 0; o >>= 1) sm += __shfl_xor_sync(0xffffffffu, sm, o);
        float inv = 1.f/sm;
        alpha_out[(b*NH_+wid)*S_ + lane]      = e0*inv;
        alpha_out[(b*NH_+wid)*S_ + lane + 32] = e1*inv;
    }
}

// ---------------- context = alpha @ states ------------------------------------
__global__ __launch_bounds__(512) void k_context(const float* __restrict__ states,
                                                 const float* __restrict__ alpha_in,
                                                 float* __restrict__ context){
    __shared__ float als[NH_*S_];
    int b = blockIdx.x, tid = threadIdx.x;
    if (tid < NH_*S_) als[tid] = alpha_in[b*NH_*S_ + tid];
    __syncthreads();
    float a0[NH_], a1[NH_];
    #pragma unroll
    for (int h = 0; h < NH_; h++){ a0[h] = 0.f; a1[h] = 0.f; }
    const float* st = states + (size_t)b*S_*2*H_;
    for (int s = 0; s < S_; s++){
        float v0 = st[s*2*H_ + tid];
        float v1 = st[s*2*H_ + H_ + tid];
        #pragma unroll
        for (int h = 0; h < NH_; h++){
            float a = als[h*S_+s];
            a0[h] += a*v0; a1[h] += a*v1;
        }
    }
    float* cb = context + (size_t)b*NH_*2*H_;
    #pragma unroll
    for (int h = 0; h < NH_; h++){
        cb[h*2*H_ + tid]      = a0[h];
        cb[h*2*H_ + H_ + tid] = a1[h];
    }
}

// ---------------- final linear + softmax --------------------------------------
__global__ __launch_bounds__(512) void k_final(const float* __restrict__ context,
                                               const float* __restrict__ lin_w,
                                               const float* __restrict__ lin_b,
                                               float* __restrict__ out){
    __shared__ float red[OUT_];
    int b = blockIdx.x, tid = threadIdx.x, w = tid >> 5, lane = tid & 31;
    const float* cx = context + (size_t)b*4096;
    const float* lw = lin_w + (size_t)w*4096;
    float acc = 0.f;
    for (int k = lane; k < 4096; k += 32) acc += cx[k]*lw[k];
    #pragma unroll
    for (int o = 16; o > 0; o >>= 1) acc += __shfl_xor_sync(0xffffffffu, acc, o);
    if (lane == 0) red[w] = acc + lin_b[w];
    __syncthreads();
    if (tid < 32){
        float v = (lane < OUT_) ? red[lane] : -1e30f;
        float mx = v;
        #pragma unroll
        for (int o = 16; o > 0; o >>= 1) mx = fmaxf(mx, __shfl_xor_sync(0xffffffffu, mx, o));
        float e = (lane < OUT_) ? expf(v - mx) : 0.f;
        float sm = e;
        #pragma unroll
        for (int o = 16; o > 0; o >>= 1) sm += __shfl_xor_sync(0xffffffffu, sm, o);
        if (lane < OUT_) out[b*OUT_ + lane] = e/sm;
    }
}

// ---------------- launch ------------------------------------------------------
extern "C" void kernel_launch(void* const* d_in, const int* in_sizes, int n_in,
                              void* d_out, int out_size){
    const float* inputs  = (const float*)d_in[0];
    const float* conv_w  = (const float*)d_in[2];
    const float* conv_b  = (const float*)d_in[3];
    const float* w_embed = (const float*)d_in[4];
    const float* w_ih_f  = (const float*)d_in[5];
    const float* w_hh_f  = (const float*)d_in[6];
    const float* b_ih_f  = (const float*)d_in[7];
    const float* b_hh_f  = (const float*)d_in[8];
    const float* w_ih_b  = (const float*)d_in[9];
    const float* w_hh_b  = (const float*)d_in[10];
    const float* b_ih_b  = (const float*)d_in[11];
    const float* b_hh_b  = (const float*)d_in[12];
    const float* att_w1  = (const float*)d_in[13];
    const float* att_w2  = (const float*)d_in[14];
    const float* lin_w   = (const float*)d_in[15];
    const float* lin_b   = (const float*)d_in[16];

    float* out     = (float*)d_out;
    float* states  = out + STATES_OFF;
    float* context = out + CONTEXT_OFF;
    float* alpha   = out + ALPHA_OFF;

    void *p_vec, *p_emb, *p_xg, *p_m1;
    cudaGetSymbolAddress(&p_vec, g_vec);
    cudaGetSymbolAddress(&p_emb, g_emb);
    cudaGetSymbolAddress(&p_xg,  g_xg);
    cudaGetSymbolAddress(&p_m1,  g_m1);
    float* vec = (float*)p_vec;
    float* emb = (float*)p_emb;
    float* xg0 = (float*)p_xg;
    float* m1  = (float*)p_m1;

    const int conv_smem = P_*D_*4;                     // 65536
    const int gru_smem  = 49152*4 + 16*128*16;         // 192KB + 32KB = 229376
    cudaFuncSetAttribute(k_conv_vec, cudaFuncAttributeMaxDynamicSharedMemorySize, conv_smem);
    cudaFuncSetAttribute(k_gru,      cudaFuncAttributeMaxDynamicSharedMemorySize, gru_smem);

    // 1) conv + weighted-sum (inputs read once)
    k_conv_vec<<<BS_, 256, conv_smem>>>(inputs, conv_w, conv_b);
    // 2) emb = clip(vec @ w_embed^T)
    k_sgemm<<<dim3(E_/128, BS_/128), 256>>>(vec, w_embed, w_embed, emb,
                                            BS_, E_, D_, nullptr, nullptr, 1, 0);
    // 3) xg = emb([S,B] permuted) @ w_ih^T + b_ih, BOTH directions in one launch
    k_sgemm<<<dim3(H3_/128, BS_/128, 2), 256>>>(emb, w_ih_f, w_ih_b, xg0,
                                                BS_, H3_, E_, b_ih_f, b_ih_b, 0, 1);
    // 4) persistent bidirectional GRU -> states (written straight into d_out)
    k_gru<<<128, 256, gru_smem>>>(w_hh_f, w_hh_b, b_hh_f, b_hh_b, states);
    // 5) m1 = clip(states @ att_w1^T)
    k_sgemm<<<dim3(A_/128, BS_/128), 256>>>(states, att_w1, att_w1, m1,
                                            BS_, A_, 2*H_, nullptr, nullptr, 1, 0);
    // 6) alpha = softmax_S(m1 @ att_w2^T), transposed to [B,NH,S]
    k_alpha<<<B_, 256>>>(att_w2, alpha);
    // 7) context
    k_context<<<B_, 512>>>(states, alpha, context);
    // 8) out = softmax(context @ lin_w^T + lin_b)
    k_final<<<B_, 512>>>(context, lin_w, lin_b, out);
}